// round 2
// baseline (speedup 1.0000x reference)
#include <cuda_runtime.h>
#include <math.h>

#define BB 8
#define CC 256
#define HH 128
#define WW 128
#define NN (HH*WW)          // 16384
#define NPOS 256
#define NHARD 96
#define NRAND 32
#define TEMP_INV (1.0f/0.07f)

// ---------------- scratch (static device globals; no allocation) ------------
__device__ float g_rgbT[BB*NN*CC];      // normalized rgb, [b][pixel][channel]
__device__ float g_pos[BB*NN];
__device__ float g_lse[BB*NN];
__device__ float g_maxneg[BB*NN];
__device__ float g_lse_hard[BB*NPOS];
__device__ float g_max_hard[BB*NPOS];
__device__ float g_acc[3];              // loss_sum, mask_sum, correct_sum

// ---------------- kernel 1: normalize + transpose rgb -> g_rgbT --------------
// block = 256 threads handles 32 pixels (contiguous along W) of one batch.
__global__ __launch_bounds__(256) void k_norm_t(const float* __restrict__ in) {
    __shared__ float s_tile[CC*33];
    __shared__ float s_red[8*33];
    __shared__ float s_inv[32];
    const int tid = threadIdx.x;
    const int tx = tid & 31;        // pixel in tile
    const int ty = tid >> 5;        // channel group
    const int blocksPerBatch = NN/32;
    const int b  = blockIdx.x / blocksPerBatch;
    const int n0 = (blockIdx.x % blocksPerBatch) * 32;

    if (blockIdx.x == 0 && tid < 3) g_acc[tid] = 0.0f;   // fold k_init

    const float* src = in + b*CC*NN + n0;
    #pragma unroll
    for (int i = 0; i < 32; i++) {
        int c = i*8 + ty;
        s_tile[c*33 + tx] = src[c*NN + tx];      // coalesced 128B
    }
    __syncthreads();

    float ss = 0.0f;
    #pragma unroll
    for (int j = 0; j < 32; j++) {
        float v = s_tile[(ty*32 + j)*33 + tx];
        ss += v*v;
    }
    s_red[ty*33 + tx] = ss;
    __syncthreads();
    if (ty == 0) {
        float t = 0.0f;
        #pragma unroll
        for (int j = 0; j < 8; j++) t += s_red[j*33 + tx];
        s_inv[tx] = 1.0f / fmaxf(sqrtf(t), 1e-12f);
    }
    __syncthreads();

    // write transposed+normalized rows: 64 threads per pixel (float4)
    float* dst = g_rgbT + (b*NN + n0)*CC;
    const int cb = tid & 63;
    const int pq = tid >> 6;
    #pragma unroll
    for (int it = 0; it < 8; it++) {
        int px = it*4 + pq;
        float inv = s_inv[px];
        float4 v;
        v.x = s_tile[(cb*4+0)*33 + px] * inv;
        v.y = s_tile[(cb*4+1)*33 + px] * inv;
        v.z = s_tile[(cb*4+2)*33 + px] * inv;
        v.w = s_tile[(cb*4+3)*33 + px] * inv;
        reinterpret_cast<float4*>(dst + px*CC)[cb] = v;
    }
}

// ---------------- kernel 2: main per-pixel pass -------------------------------
__device__ __forceinline__ int corner_idx(int xx, int yy, float& w) {
    bool v = (xx >= 0) & (xx < WW) & (yy >= 0) & (yy < HH);
    if (!v) w = 0.0f;
    int cx = min(max(xx, 0), WW-1);
    int cy = min(max(yy, 0), HH-1);
    return cy*WW + cx;
}

__global__ __launch_bounds__(256) void k_main(const float* __restrict__ dep,
                                              const float* __restrict__ proj,
                                              const int*   __restrict__ rand_idx) {
    extern __shared__ float sm[];
    float* s_dep  = sm;                       // 256*33
    float* s_rand = sm + CC*33;               // 32*256 (16B aligned: 8448 floats)
    float* s_sim  = s_rand + NRAND*CC;        // 32*33
    float* s_pos  = s_sim + 32*33;            // 32
    float* s_inv  = s_pos + 32;               // 32
    float* s_red  = s_inv + 32;               // 8*33

    const int tid = threadIdx.x;
    const int tx = tid & 31;
    const int ty = tid >> 5;
    const int blocksPerBatch = NN/32;
    const int b  = blockIdx.x / blocksPerBatch;
    const int n0 = (blockIdx.x % blocksPerBatch) * 32;

    // stage dep tile (coalesced)
    const float* dsrc = dep + b*CC*NN + n0;
    #pragma unroll
    for (int i = 0; i < 32; i++) {
        int c = i*8 + ty;
        s_dep[c*33 + tx] = dsrc[c*NN + tx];
    }
    // stage rand vectors (already normalized rows of g_rgbT)
    {
        int k = tid >> 3, part = tid & 7;
        int ridx = rand_idx[b*NRAND + k];
        const float4* row = reinterpret_cast<const float4*>(g_rgbT + (b*NN + ridx)*CC);
        float4* dstr = reinterpret_cast<float4*>(s_rand + k*CC);
        #pragma unroll
        for (int i = 0; i < 8; i++) dstr[part + 8*i] = row[part + 8*i];
    }
    __syncthreads();

    // depth inverse norms per pixel
    float ss = 0.0f;
    #pragma unroll
    for (int j = 0; j < 32; j++) {
        float v = s_dep[(ty*32 + j)*33 + tx];
        ss += v*v;
    }
    s_red[ty*33 + tx] = ss;
    __syncthreads();
    if (ty == 0) {
        float t = 0.0f;
        #pragma unroll
        for (int j = 0; j < 8; j++) t += s_red[j*33 + tx];
        s_inv[tx] = 1.0f / fmaxf(sqrtf(t), 1e-12f);
    }
    __syncthreads();

    // ---- phase 2: pos_sim (warp per pixel, 4 pixels per warp) ----
    const float* projU = proj + b*2*NN;
    const float* projV = projU + NN;
    #pragma unroll
    for (int q = 0; q < 4; q++) {
        int px = ty*4 + q;
        int n  = n0 + px;
        float pu = projU[n], pv = projV[n];
        float x0f = floorf(pu), y0f = floorf(pv);
        float wx = pu - x0f, wy = pv - y0f;
        int x0 = (int)x0f, y0 = (int)y0f;
        float w00 = (1.0f-wx)*(1.0f-wy), w10 = wx*(1.0f-wy);
        float w01 = (1.0f-wx)*wy,        w11 = wx*wy;
        int i00 = corner_idx(x0,   y0,   w00);
        int i10 = corner_idx(x0+1, y0,   w10);
        int i01 = corner_idx(x0,   y0+1, w01);
        int i11 = corner_idx(x0+1, y0+1, w11);
        const float* r00 = g_rgbT + (b*NN + i00)*CC;
        const float* r10 = g_rgbT + (b*NN + i10)*CC;
        const float* r01 = g_rgbT + (b*NN + i01)*CC;
        const float* r11 = g_rgbT + (b*NN + i11)*CC;
        float pacc = 0.0f;
        #pragma unroll
        for (int jj = 0; jj < 8; jj++) {
            int c = tx + jj*32;
            float d = s_dep[c*33 + px];
            float r = w00*r00[c] + w10*r10[c] + w01*r01[c] + w11*r11[c];
            pacc += d*r;
        }
        #pragma unroll
        for (int o = 16; o; o >>= 1) pacc += __shfl_xor_sync(0xffffffffu, pacc, o);
        if (tx == 0) s_pos[px] = pacc;
    }

    // ---- phase 3: 32 rand dots (lane = pixel, warp owns 4 k's) ----
    {
        float a0 = 0.f, a1 = 0.f, a2 = 0.f, a3 = 0.f;
        const float4* rk0 = reinterpret_cast<const float4*>(s_rand + (ty*4+0)*CC);
        const float4* rk1 = reinterpret_cast<const float4*>(s_rand + (ty*4+1)*CC);
        const float4* rk2 = reinterpret_cast<const float4*>(s_rand + (ty*4+2)*CC);
        const float4* rk3 = reinterpret_cast<const float4*>(s_rand + (ty*4+3)*CC);
        #pragma unroll 8
        for (int c4 = 0; c4 < 64; c4++) {
            int c = c4*4;
            float d0 = s_dep[(c+0)*33 + tx];
            float d1 = s_dep[(c+1)*33 + tx];
            float d2 = s_dep[(c+2)*33 + tx];
            float d3 = s_dep[(c+3)*33 + tx];
            float4 r;
            r = rk0[c4]; a0 += d0*r.x; a0 += d1*r.y; a0 += d2*r.z; a0 += d3*r.w;
            r = rk1[c4]; a1 += d0*r.x; a1 += d1*r.y; a1 += d2*r.z; a1 += d3*r.w;
            r = rk2[c4]; a2 += d0*r.x; a2 += d1*r.y; a2 += d2*r.z; a2 += d3*r.w;
            r = rk3[c4]; a3 += d0*r.x; a3 += d1*r.y; a3 += d2*r.z; a3 += d3*r.w;
        }
        s_sim[(ty*4+0)*33 + tx] = a0;
        s_sim[(ty*4+1)*33 + tx] = a1;
        s_sim[(ty*4+2)*33 + tx] = a2;
        s_sim[(ty*4+3)*33 + tx] = a3;
    }
    __syncthreads();

    // ---- phase 4: per-pixel logsumexp / max, lane-parallel over negatives ----
    // warp ty handles pixels ty*4..ty*4+3; lane k owns negative k.
    #pragma unroll
    for (int q = 0; q < 4; q++) {
        int px = ty*4 + q;
        float scale = s_inv[px] * TEMP_INV;   // > 0, monotonic
        float pos = s_pos[px] * scale;
        float v = s_sim[tx*33 + px] * scale;  // (tx+px)%32 -> conflict-free
        float mneg = v;
        #pragma unroll
        for (int o = 16; o; o >>= 1) mneg = fmaxf(mneg, __shfl_xor_sync(0xffffffffu, mneg, o));
        float m = fmaxf(pos, mneg);
        float e = expf(v - m);
        #pragma unroll
        for (int o = 16; o; o >>= 1) e += __shfl_xor_sync(0xffffffffu, e, o);
        if (tx == 0) {
            int gp = b*NN + n0 + px;
            g_pos[gp]    = pos;
            g_lse[gp]    = m + logf(e + expf(pos - m));
            g_maxneg[gp] = mneg;
        }
    }
}

// ---------------- kernel 3: hard negatives at grid points --------------------
// block = 256 = 8 warps per (b, grid-point). Each warp: 12 h in 3 groups of 4
// concurrent accumulators with float4 loads (MLP >= 8 LDG.128 in flight).
__global__ __launch_bounds__(256) void k_hard(const float* __restrict__ dep,
                                              const float* __restrict__ proj,
                                              const int*   __restrict__ offu,
                                              const int*   __restrict__ offv) {
    __shared__ float s_depv[CC];
    __shared__ float s_hsim[NHARD];
    __shared__ float s_red2[8];
    __shared__ float s_invd;
    const int tid = threadIdx.x;
    const int tx = tid & 31;
    const int ty = tid >> 5;
    const int b = blockIdx.x >> 8;
    const int p = blockIdx.x & 255;
    const int gh = (p >> 4) * 8;
    const int gw = (p & 15) * 8;
    const int ng = gh*WW + gw;

    s_depv[tid] = dep[b*CC*NN + tid*NN + ng];
    __syncthreads();
    {
        float v = s_depv[tid];
        float ss = v*v;
        #pragma unroll
        for (int o = 16; o; o >>= 1) ss += __shfl_xor_sync(0xffffffffu, ss, o);
        if (tx == 0) s_red2[ty] = ss;
    }
    __syncthreads();
    if (tid == 0) {
        float t = 0.0f;
        #pragma unroll
        for (int j = 0; j < 8; j++) t += s_red2[j];
        s_invd = 1.0f / fmaxf(sqrtf(t), 1e-12f);
    }
    __syncthreads();
    const float invd = s_invd;

    float pu = proj[b*2*NN + ng];
    float pv = proj[b*2*NN + NN + ng];
    int posu = (int)fminf(fmaxf(pu, 0.0f), (float)(WW-1));
    int posv = (int)fminf(fmaxf(pv, 0.0f), (float)(HH-1));

    const float4* dv = reinterpret_cast<const float4*>(s_depv);
    #pragma unroll
    for (int g3 = 0; g3 < 3; g3++) {
        int hbase = ty*12 + g3*4;
        const float4* r[4];
        #pragma unroll
        for (int j = 0; j < 4; j++) {
            int h = hbase + j;
            int ou = offu[(b*NHARD + h)*NPOS + p];
            int ov = offv[(b*NHARD + h)*NPOS + p];
            if (ou == 0 && ov == 0) ou = 1;
            int hu = min(max(posu + ou, 0), WW-1);
            int hv = min(max(posv + ov, 0), HH-1);
            r[j] = reinterpret_cast<const float4*>(g_rgbT + (b*NN + hv*WW + hu)*CC);
        }
        float a0 = 0.f, a1 = 0.f, a2 = 0.f, a3 = 0.f;
        #pragma unroll
        for (int jj = 0; jj < 2; jj++) {
            int c4 = jj*32 + tx;
            float4 d = dv[c4];
            float4 v0 = r[0][c4];
            float4 v1 = r[1][c4];
            float4 v2 = r[2][c4];
            float4 v3 = r[3][c4];
            a0 += d.x*v0.x; a0 += d.y*v0.y; a0 += d.z*v0.z; a0 += d.w*v0.w;
            a1 += d.x*v1.x; a1 += d.y*v1.y; a1 += d.z*v1.z; a1 += d.w*v1.w;
            a2 += d.x*v2.x; a2 += d.y*v2.y; a2 += d.z*v2.z; a2 += d.w*v2.w;
            a3 += d.x*v3.x; a3 += d.y*v3.y; a3 += d.z*v3.z; a3 += d.w*v3.w;
        }
        #pragma unroll
        for (int o = 16; o; o >>= 1) {
            a0 += __shfl_xor_sync(0xffffffffu, a0, o);
            a1 += __shfl_xor_sync(0xffffffffu, a1, o);
            a2 += __shfl_xor_sync(0xffffffffu, a2, o);
            a3 += __shfl_xor_sync(0xffffffffu, a3, o);
        }
        if (tx == 0) {
            float sc = invd * TEMP_INV;
            s_hsim[hbase+0] = a0 * sc;
            s_hsim[hbase+1] = a1 * sc;
            s_hsim[hbase+2] = a2 * sc;
            s_hsim[hbase+3] = a3 * sc;
        }
    }
    __syncthreads();

    // parallel 96-wide logsumexp / max (warp 0, 3 values per lane)
    if (tid < 32) {
        float v0 = s_hsim[tx];
        float v1 = s_hsim[tx + 32];
        float v2 = s_hsim[tx + 64];
        float m = fmaxf(fmaxf(v0, v1), v2);
        #pragma unroll
        for (int o = 16; o; o >>= 1) m = fmaxf(m, __shfl_xor_sync(0xffffffffu, m, o));
        float se = expf(v0 - m) + expf(v1 - m) + expf(v2 - m);
        #pragma unroll
        for (int o = 16; o; o >>= 1) se += __shfl_xor_sync(0xffffffffu, se, o);
        if (tx == 0) {
            g_lse_hard[b*NPOS + p] = m + logf(se);
            g_max_hard[b*NPOS + p] = m;
        }
    }
}

// ---------------- kernel 4: loss/accuracy reduction ---------------------------
__global__ __launch_bounds__(256) void k_loss(const float* __restrict__ valid) {
    __shared__ float sA[8], sB[8], sC[8];
    const int g = blockIdx.x * 256 + threadIdx.x;
    const int b = g >> 14;
    const int n = g & (NN-1);
    const int vq = n >> 7;
    const int u  = n & 127;

    float lse = g_lse[g];
    float pos = g_pos[g];
    float mx  = g_maxneg[g];
    if (((vq & 7) == 0) && ((u & 7) == 0)) {
        int p = (vq >> 3) * 16 + (u >> 3);
        float lh = g_lse_hard[b*NPOS + p];
        float mh = g_max_hard[b*NPOS + p];
        float m = fmaxf(lse, lh);
        lse = m + logf(expf(lse - m) + expf(lh - m));
        mx = fmaxf(mx, mh);
    }
    float mask = valid[g];
    float lossp = (lse - pos) * mask;
    float corr = (pos > mx && mask > 0.5f) ? 1.0f : 0.0f;
    float mk = mask;

    #pragma unroll
    for (int o = 16; o; o >>= 1) {
        lossp += __shfl_xor_sync(0xffffffffu, lossp, o);
        mk    += __shfl_xor_sync(0xffffffffu, mk,    o);
        corr  += __shfl_xor_sync(0xffffffffu, corr,  o);
    }
    if ((threadIdx.x & 31) == 0) {
        sA[threadIdx.x >> 5] = lossp;
        sB[threadIdx.x >> 5] = mk;
        sC[threadIdx.x >> 5] = corr;
    }
    __syncthreads();
    if (threadIdx.x == 0) {
        float a = 0.f, bb2 = 0.f, c2 = 0.f;
        #pragma unroll
        for (int j = 0; j < 8; j++) { a += sA[j]; bb2 += sB[j]; c2 += sC[j]; }
        atomicAdd(&g_acc[0], a);
        atomicAdd(&g_acc[1], bb2);
        atomicAdd(&g_acc[2], c2);
    }
}

// ---------------- kernel 5: epilogue ------------------------------------------
__global__ void k_out(float* out) {
    float denom = fmaxf(g_acc[1], 1.0f);
    out[0] = g_acc[0] / denom;
    out[1] = g_acc[2] / denom * 100.0f;
}

// ---------------- launch -------------------------------------------------------
extern "C" void kernel_launch(void* const* d_in, const int* in_sizes, int n_in,
                              void* d_out, int out_size) {
    const float* rgb   = (const float*)d_in[0];
    const float* dep   = (const float*)d_in[1];
    const float* proj  = (const float*)d_in[2];
    const float* valid = (const float*)d_in[3];
    const int*   ridx  = (const int*)d_in[4];
    const int*   offu  = (const int*)d_in[5];
    const int*   offv  = (const int*)d_in[6];
    float* out = (float*)d_out;

    const int smem_main = (CC*33 + NRAND*CC + 32*33 + 32 + 32 + 8*33) * (int)sizeof(float);
    cudaFuncSetAttribute(k_main, cudaFuncAttributeMaxDynamicSharedMemorySize, smem_main);

    k_norm_t<<<BB*NN/32, 256>>>(rgb);
    k_main<<<BB*NN/32, 256, smem_main>>>(dep, proj, ridx);
    k_hard<<<BB*NPOS, 256>>>(dep, proj, offu, offv);
    k_loss<<<BB*NN/256, 256>>>(valid);
    k_out<<<1, 1>>>(out);
}

// round 3
// speedup vs baseline: 1.1906x; 1.1906x over previous
#include <cuda_runtime.h>
#include <math.h>

#define BB 8
#define CC 256
#define HH 128
#define WW 128
#define NN (HH*WW)          // 16384
#define NPOS 256
#define NHARD 96
#define NRAND 32
#define TEMP_INV (1.0f/0.07f)

typedef unsigned long long u64;

__device__ __forceinline__ u64 fma2(u64 a, u64 b, u64 c) {
    u64 d;
    asm("fma.rn.f32x2 %0,%1,%2,%3;" : "=l"(d) : "l"(a), "l"(b), "l"(c));
    return d;
}
__device__ __forceinline__ float2 unpack2(u64 v) {
    float2 f;
    asm("mov.b64 {%0,%1},%2;" : "=f"(f.x), "=f"(f.y) : "l"(v));
    return f;
}

// ---------------- scratch (static device globals; no allocation) ------------
__device__ float g_rgbT[BB*NN*CC];      // normalized rgb, [b][pixel][channel]
__device__ float g_depGrid[BB*NPOS*CC]; // normalized*TEMP_INV dep at grid pts
__device__ float g_pos[BB*NN];
__device__ float g_lse[BB*NN];
__device__ float g_maxneg[BB*NN];
__device__ float g_lse_hard[BB*NPOS];
__device__ float g_max_hard[BB*NPOS];
__device__ float g_acc[3];              // loss_sum, mask_sum, correct_sum

// ---------------- kernel 1: normalize + transpose rgb -> g_rgbT --------------
__global__ __launch_bounds__(256) void k_norm_t(const float* __restrict__ in) {
    __shared__ float s_tile[CC*33];
    __shared__ float s_red[8*33];
    __shared__ float s_inv[32];
    const int tid = threadIdx.x;
    const int tx = tid & 31;        // pixel in tile
    const int ty = tid >> 5;        // channel group
    const int blocksPerBatch = NN/32;
    const int b  = blockIdx.x / blocksPerBatch;
    const int n0 = (blockIdx.x % blocksPerBatch) * 32;

    if (blockIdx.x == 0 && tid < 3) g_acc[tid] = 0.0f;

    const float* src = in + b*CC*NN + n0;
    #pragma unroll 8
    for (int i = 0; i < 32; i++) {
        int c = i*8 + ty;
        s_tile[c*33 + tx] = src[c*NN + tx];
    }
    __syncthreads();

    float ss = 0.0f;
    #pragma unroll
    for (int j = 0; j < 32; j++) {
        float v = s_tile[(ty*32 + j)*33 + tx];
        ss += v*v;
    }
    s_red[ty*33 + tx] = ss;
    __syncthreads();
    if (ty == 0) {
        float t = 0.0f;
        #pragma unroll
        for (int j = 0; j < 8; j++) t += s_red[j*33 + tx];
        s_inv[tx] = 1.0f / fmaxf(sqrtf(t), 1e-12f);
    }
    __syncthreads();

    float* dst = g_rgbT + (b*NN + n0)*CC;
    const int cb = tid & 63;
    const int pq = tid >> 6;
    #pragma unroll
    for (int it = 0; it < 8; it++) {
        int px = it*4 + pq;
        float inv = s_inv[px];
        float4 v;
        v.x = s_tile[(cb*4+0)*33 + px] * inv;
        v.y = s_tile[(cb*4+1)*33 + px] * inv;
        v.z = s_tile[(cb*4+2)*33 + px] * inv;
        v.w = s_tile[(cb*4+3)*33 + px] * inv;
        reinterpret_cast<float4*>(dst + px*CC)[cb] = v;
    }
}

// ---------------- kernel 2: main pass, 64 pixels per block -------------------
#define DSTR 260   // padded pixel-major row stride (floats), 16B aligned

__device__ __forceinline__ int corner_idx(int xx, int yy, float& w) {
    bool v = (xx >= 0) & (xx < WW) & (yy >= 0) & (yy < HH);
    if (!v) w = 0.0f;
    int cx = min(max(xx, 0), WW-1);
    int cy = min(max(yy, 0), HH-1);
    return cy*WW + cx;
}

__global__ __launch_bounds__(256) void k_main(const float* __restrict__ dep,
                                              const float* __restrict__ proj,
                                              const int*   __restrict__ rand_idx) {
    extern __shared__ float sm[];
    float* s_dep2 = sm;                        // 64 * 260, pixel-major
    float* s_rand = s_dep2 + 64*DSTR;          // 32 * 256
    float* s_sim  = s_rand + NRAND*CC;         // 32 * 65
    float* s_pos  = s_sim + NRAND*65;          // 64
    float* s_inv  = s_pos + 64;                // 64
    float* s_red  = s_inv + 64;                // 4 * 65

    const int tid = threadIdx.x;
    const int tx  = tid & 31;
    const int ty  = tid >> 5;                  // warp id 0..7
    const int blocksPerBatch = NN/64;
    const int b  = blockIdx.x / blocksPerBatch;
    const int n0 = (blockIdx.x % blocksPerBatch) * 64;

    // ---- stage dep tile pixel-major + partial norms ----
    {
        const int px = tid & 63;               // pixel 0..63
        const int cg = tid >> 6;               // channel group 0..3
        const float* dsrc = dep + b*CC*NN + n0 + px;
        float ss = 0.0f;
        #pragma unroll 16
        for (int i = 0; i < 64; i++) {
            int c = i*4 + cg;
            float v = dsrc[c*NN];
            s_dep2[px*DSTR + c] = v;
            ss += v*v;
        }
        s_red[cg*65 + px] = ss;
    }
    // ---- stage rand vectors ----
    {
        int k = tid >> 3, part = tid & 7;
        int ridx = rand_idx[b*NRAND + k];
        const float4* row = reinterpret_cast<const float4*>(g_rgbT + (b*NN + ridx)*CC);
        float4* dstr = reinterpret_cast<float4*>(s_rand + k*CC);
        #pragma unroll
        for (int i = 0; i < 8; i++) dstr[part + 8*i] = row[part + 8*i];
    }
    __syncthreads();
    if (tid < 64) {
        float t = s_red[tid] + s_red[65 + tid] + s_red[2*65 + tid] + s_red[3*65 + tid];
        s_inv[tid] = 1.0f / fmaxf(sqrtf(t), 1e-12f);
    }
    __syncthreads();

    // ---- phase 2: pos_sim (warp handles 8 pixels) ----
    const float* projU = proj + b*2*NN;
    const float* projV = projU + NN;
    const float4* dv4 = reinterpret_cast<const float4*>(s_dep2);
    #pragma unroll
    for (int q = 0; q < 8; q++) {
        int px = ty*8 + q;
        int n  = n0 + px;
        float pu = projU[n], pv = projV[n];
        float x0f = floorf(pu), y0f = floorf(pv);
        float wx = pu - x0f, wy = pv - y0f;
        int x0 = (int)x0f, y0 = (int)y0f;
        float w00 = (1.0f-wx)*(1.0f-wy), w10 = wx*(1.0f-wy);
        float w01 = (1.0f-wx)*wy,        w11 = wx*wy;
        int i00 = corner_idx(x0,   y0,   w00);
        int i10 = corner_idx(x0+1, y0,   w10);
        int i01 = corner_idx(x0,   y0+1, w01);
        int i11 = corner_idx(x0+1, y0+1, w11);
        const float4* r00 = reinterpret_cast<const float4*>(g_rgbT + (b*NN + i00)*CC);
        const float4* r10 = reinterpret_cast<const float4*>(g_rgbT + (b*NN + i10)*CC);
        const float4* r01 = reinterpret_cast<const float4*>(g_rgbT + (b*NN + i01)*CC);
        const float4* r11 = reinterpret_cast<const float4*>(g_rgbT + (b*NN + i11)*CC);
        float pacc = 0.0f;
        #pragma unroll
        for (int jj = 0; jj < 2; jj++) {
            int c4 = tx + jj*32;
            float4 d  = dv4[px*(DSTR/4) + c4];
            float4 a00 = r00[c4], a10 = r10[c4], a01 = r01[c4], a11 = r11[c4];
            pacc += d.x*(w00*a00.x + w10*a10.x + w01*a01.x + w11*a11.x);
            pacc += d.y*(w00*a00.y + w10*a10.y + w01*a01.y + w11*a11.y);
            pacc += d.z*(w00*a00.z + w10*a10.z + w01*a01.z + w11*a11.z);
            pacc += d.w*(w00*a00.w + w10*a10.w + w01*a01.w + w11*a11.w);
        }
        #pragma unroll
        for (int o = 16; o; o >>= 1) pacc += __shfl_xor_sync(0xffffffffu, pacc, o);
        if (tx == 0) s_pos[px] = pacc;
    }

    // ---- phase 3: rand dots, 2 pixels/lane, 4 k's/warp, f32x2 FMA ----
    {
        const ulonglong2* dA = reinterpret_cast<const ulonglong2*>(s_dep2 + tx*DSTR);
        const ulonglong2* dB = reinterpret_cast<const ulonglong2*>(s_dep2 + (tx+32)*DSTR);
        const ulonglong2* rp0 = reinterpret_cast<const ulonglong2*>(s_rand + (ty*4+0)*CC);
        const ulonglong2* rp1 = reinterpret_cast<const ulonglong2*>(s_rand + (ty*4+1)*CC);
        const ulonglong2* rp2 = reinterpret_cast<const ulonglong2*>(s_rand + (ty*4+2)*CC);
        const ulonglong2* rp3 = reinterpret_cast<const ulonglong2*>(s_rand + (ty*4+3)*CC);
        u64 aA0=0, aA1=0, aA2=0, aA3=0;
        u64 aB0=0, aB1=0, aB2=0, aB3=0;
        #pragma unroll 8
        for (int c4 = 0; c4 < 64; c4++) {
            ulonglong2 da = dA[c4];
            ulonglong2 db = dB[c4];
            ulonglong2 r0 = rp0[c4], r1 = rp1[c4], r2 = rp2[c4], r3 = rp3[c4];
            aA0 = fma2(da.x, r0.x, aA0); aA0 = fma2(da.y, r0.y, aA0);
            aA1 = fma2(da.x, r1.x, aA1); aA1 = fma2(da.y, r1.y, aA1);
            aA2 = fma2(da.x, r2.x, aA2); aA2 = fma2(da.y, r2.y, aA2);
            aA3 = fma2(da.x, r3.x, aA3); aA3 = fma2(da.y, r3.y, aA3);
            aB0 = fma2(db.x, r0.x, aB0); aB0 = fma2(db.y, r0.y, aB0);
            aB1 = fma2(db.x, r1.x, aB1); aB1 = fma2(db.y, r1.y, aB1);
            aB2 = fma2(db.x, r2.x, aB2); aB2 = fma2(db.y, r2.y, aB2);
            aB3 = fma2(db.x, r3.x, aB3); aB3 = fma2(db.y, r3.y, aB3);
        }
        float2 f;
        f = unpack2(aA0); s_sim[(ty*4+0)*65 + tx]      = f.x + f.y;
        f = unpack2(aA1); s_sim[(ty*4+1)*65 + tx]      = f.x + f.y;
        f = unpack2(aA2); s_sim[(ty*4+2)*65 + tx]      = f.x + f.y;
        f = unpack2(aA3); s_sim[(ty*4+3)*65 + tx]      = f.x + f.y;
        f = unpack2(aB0); s_sim[(ty*4+0)*65 + tx + 32] = f.x + f.y;
        f = unpack2(aB1); s_sim[(ty*4+1)*65 + tx + 32] = f.x + f.y;
        f = unpack2(aB2); s_sim[(ty*4+2)*65 + tx + 32] = f.x + f.y;
        f = unpack2(aB3); s_sim[(ty*4+3)*65 + tx + 32] = f.x + f.y;
    }
    __syncthreads();

    // ---- grid-point dep dump (normalized * TEMP_INV) ----
    {
        int v_row = n0 / WW;
        int u0 = n0 % WW;
        if ((v_row & 7) == 0) {
            int px = ty*8;   // u%8==0 positions within the 64-px tile
            int p = ((v_row >> 3) << 4) + ((u0 + px) >> 3);
            float sc = s_inv[px] * TEMP_INV;
            float* dst = g_depGrid + (b*NPOS + p)*CC;
            #pragma unroll
            for (int jj = 0; jj < 8; jj++) {
                int c = tx + jj*32;
                dst[c] = s_dep2[px*DSTR + c] * sc;
            }
        }
    }

    // ---- phase 4: per-pixel logsumexp / max, lane-parallel over negatives ----
    #pragma unroll
    for (int q = 0; q < 8; q++) {
        int px = ty*8 + q;
        float scale = s_inv[px] * TEMP_INV;
        float pos = s_pos[px] * scale;
        float v = s_sim[tx*65 + px] * scale;
        float mneg = v;
        #pragma unroll
        for (int o = 16; o; o >>= 1) mneg = fmaxf(mneg, __shfl_xor_sync(0xffffffffu, mneg, o));
        float m = fmaxf(pos, mneg);
        float e = expf(v - m);
        #pragma unroll
        for (int o = 16; o; o >>= 1) e += __shfl_xor_sync(0xffffffffu, e, o);
        if (tx == 0) {
            int gp = b*NN + n0 + px;
            g_pos[gp]    = pos;
            g_lse[gp]    = m + logf(e + expf(pos - m));
            g_maxneg[gp] = mneg;
        }
    }
}

// ---------------- kernel 3: hard negatives (dep pre-normalized) --------------
__global__ __launch_bounds__(256) void k_hard(const float* __restrict__ proj,
                                              const int*   __restrict__ offu,
                                              const int*   __restrict__ offv) {
    __shared__ float s_depv[CC];
    __shared__ float s_hsim[NHARD];
    const int tid = threadIdx.x;
    const int tx = tid & 31;
    const int ty = tid >> 5;
    const int b = blockIdx.x >> 8;
    const int p = blockIdx.x & 255;
    const int gh = (p >> 4) * 8;
    const int gw = (p & 15) * 8;
    const int ng = gh*WW + gw;

    s_depv[tid] = g_depGrid[(b*NPOS + p)*CC + tid];
    __syncthreads();

    float pu = proj[b*2*NN + ng];
    float pv = proj[b*2*NN + NN + ng];
    int posu = (int)fminf(fmaxf(pu, 0.0f), (float)(WW-1));
    int posv = (int)fminf(fmaxf(pv, 0.0f), (float)(HH-1));

    const float4* dv = reinterpret_cast<const float4*>(s_depv);
    #pragma unroll
    for (int g3 = 0; g3 < 3; g3++) {
        int hbase = ty*12 + g3*4;
        const float4* r[4];
        #pragma unroll
        for (int j = 0; j < 4; j++) {
            int h = hbase + j;
            int ou = offu[(b*NHARD + h)*NPOS + p];
            int ov = offv[(b*NHARD + h)*NPOS + p];
            if (ou == 0 && ov == 0) ou = 1;
            int hu = min(max(posu + ou, 0), WW-1);
            int hv = min(max(posv + ov, 0), HH-1);
            r[j] = reinterpret_cast<const float4*>(g_rgbT + (b*NN + hv*WW + hu)*CC);
        }
        float a0 = 0.f, a1 = 0.f, a2 = 0.f, a3 = 0.f;
        #pragma unroll
        for (int jj = 0; jj < 2; jj++) {
            int c4 = jj*32 + tx;
            float4 d = dv[c4];
            float4 v0 = r[0][c4];
            float4 v1 = r[1][c4];
            float4 v2 = r[2][c4];
            float4 v3 = r[3][c4];
            a0 += d.x*v0.x; a0 += d.y*v0.y; a0 += d.z*v0.z; a0 += d.w*v0.w;
            a1 += d.x*v1.x; a1 += d.y*v1.y; a1 += d.z*v1.z; a1 += d.w*v1.w;
            a2 += d.x*v2.x; a2 += d.y*v2.y; a2 += d.z*v2.z; a2 += d.w*v2.w;
            a3 += d.x*v3.x; a3 += d.y*v3.y; a3 += d.z*v3.z; a3 += d.w*v3.w;
        }
        #pragma unroll
        for (int o = 16; o; o >>= 1) {
            a0 += __shfl_xor_sync(0xffffffffu, a0, o);
            a1 += __shfl_xor_sync(0xffffffffu, a1, o);
            a2 += __shfl_xor_sync(0xffffffffu, a2, o);
            a3 += __shfl_xor_sync(0xffffffffu, a3, o);
        }
        if (tx == 0) {
            s_hsim[hbase+0] = a0;
            s_hsim[hbase+1] = a1;
            s_hsim[hbase+2] = a2;
            s_hsim[hbase+3] = a3;
        }
    }
    __syncthreads();

    if (tid < 32) {
        float v0 = s_hsim[tx];
        float v1 = s_hsim[tx + 32];
        float v2 = s_hsim[tx + 64];
        float m = fmaxf(fmaxf(v0, v1), v2);
        #pragma unroll
        for (int o = 16; o; o >>= 1) m = fmaxf(m, __shfl_xor_sync(0xffffffffu, m, o));
        float se = expf(v0 - m) + expf(v1 - m) + expf(v2 - m);
        #pragma unroll
        for (int o = 16; o; o >>= 1) se += __shfl_xor_sync(0xffffffffu, se, o);
        if (tx == 0) {
            g_lse_hard[b*NPOS + p] = m + logf(se);
            g_max_hard[b*NPOS + p] = m;
        }
    }
}

// ---------------- kernel 4: loss/accuracy reduction ---------------------------
__global__ __launch_bounds__(256) void k_loss(const float* __restrict__ valid) {
    __shared__ float sA[8], sB[8], sC[8];
    const int g = blockIdx.x * 256 + threadIdx.x;
    const int b = g >> 14;
    const int n = g & (NN-1);
    const int vq = n >> 7;
    const int u  = n & 127;

    float lse = g_lse[g];
    float pos = g_pos[g];
    float mx  = g_maxneg[g];
    if (((vq & 7) == 0) && ((u & 7) == 0)) {
        int p = (vq >> 3) * 16 + (u >> 3);
        float lh = g_lse_hard[b*NPOS + p];
        float mh = g_max_hard[b*NPOS + p];
        float m = fmaxf(lse, lh);
        lse = m + logf(expf(lse - m) + expf(lh - m));
        mx = fmaxf(mx, mh);
    }
    float mask = valid[g];
    float lossp = (lse - pos) * mask;
    float corr = (pos > mx && mask > 0.5f) ? 1.0f : 0.0f;
    float mk = mask;

    #pragma unroll
    for (int o = 16; o; o >>= 1) {
        lossp += __shfl_xor_sync(0xffffffffu, lossp, o);
        mk    += __shfl_xor_sync(0xffffffffu, mk,    o);
        corr  += __shfl_xor_sync(0xffffffffu, corr,  o);
    }
    if ((threadIdx.x & 31) == 0) {
        sA[threadIdx.x >> 5] = lossp;
        sB[threadIdx.x >> 5] = mk;
        sC[threadIdx.x >> 5] = corr;
    }
    __syncthreads();
    if (threadIdx.x == 0) {
        float a = 0.f, bb2 = 0.f, c2 = 0.f;
        #pragma unroll
        for (int j = 0; j < 8; j++) { a += sA[j]; bb2 += sB[j]; c2 += sC[j]; }
        atomicAdd(&g_acc[0], a);
        atomicAdd(&g_acc[1], bb2);
        atomicAdd(&g_acc[2], c2);
    }
}

// ---------------- kernel 5: epilogue ------------------------------------------
__global__ void k_out(float* out) {
    float denom = fmaxf(g_acc[1], 1.0f);
    out[0] = g_acc[0] / denom;
    out[1] = g_acc[2] / denom * 100.0f;
}

// ---------------- launch -------------------------------------------------------
extern "C" void kernel_launch(void* const* d_in, const int* in_sizes, int n_in,
                              void* d_out, int out_size) {
    const float* rgb   = (const float*)d_in[0];
    const float* dep   = (const float*)d_in[1];
    const float* proj  = (const float*)d_in[2];
    const float* valid = (const float*)d_in[3];
    const int*   ridx  = (const int*)d_in[4];
    const int*   offu  = (const int*)d_in[5];
    const int*   offv  = (const int*)d_in[6];
    float* out = (float*)d_out;

    const int smem_main = (64*DSTR + NRAND*CC + NRAND*65 + 64 + 64 + 4*65) * (int)sizeof(float);
    cudaFuncSetAttribute(k_main, cudaFuncAttributeMaxDynamicSharedMemorySize, smem_main);

    k_norm_t<<<BB*NN/32, 256>>>(rgb);
    k_main<<<BB*NN/64, 256, smem_main>>>(dep, proj, ridx);
    k_hard<<<BB*NPOS, 256>>>(proj, offu, offv);
    k_loss<<<BB*NN/256, 256>>>(valid);
    k_out<<<1, 1>>>(out);
}